// round 5
// baseline (speedup 1.0000x reference)
#include <cuda_runtime.h>
#include <math.h>
#include <stdint.h>

// ---------------------------------------------------------------------------
// DiffractionIntegration — v5
//   gemm1/gemm2: tf32 mma + fused LN/SiLU (unchanged from v4, proven)
//   gemm3: tf32 mma + FUSED structure-factor epilogue (integer-hkl power
//          tables, warp/block reduction, atomics into sf). No ff round-trip.
//   Small-batch chain: fp32 (unchanged).
// ---------------------------------------------------------------------------

#define NNODE_MAX 200000
#define BMAX      256

__device__ float g_s1[(size_t)NNODE_MAX * 256];
__device__ float g_s2[(size_t)NNODE_MAX * 128];
__device__ float g_sf[BMAX * 600];
__device__ float g_d1[BMAX * 512];
__device__ float g_d2[BMAX * 256];
__device__ float g_d3[BMAX * 512];
__device__ float g_comb[BMAX * 1024];
__device__ float g_f1[BMAX * 512];

// ---------------------------------------------------------------------------
__device__ __forceinline__ void cp16(void* dst_smem, const void* src, int bytes)
{
    uint32_t d = (uint32_t)__cvta_generic_to_shared(dst_smem);
    asm volatile("cp.async.cg.shared.global [%0], [%1], 16, %2;"
                 :: "r"(d), "l"(src), "r"(bytes) : "memory");
}

// ---------------------------------------------------------------------------
// tf32 GEMM (gemm1/gemm2): C = A@W + bias, fused row LayerNorm+SiLU.
// BM=64, BK=16, 256 threads, mma.m16n8k8, cp.async double buffering.
// ---------------------------------------------------------------------------
template<int BM, int BN, int WARPS_M, int WARPS_N, bool FUSE_LN, bool PRED_N>
__global__ __launch_bounds__(256, 2) void tf32_gemm(
    const float* __restrict__ A, const float* __restrict__ W,
    const float* __restrict__ bias, const float* __restrict__ gamma,
    const float* __restrict__ beta, float* __restrict__ C,
    int M, int N, int K)
{
    constexpr int BK   = 16;
    constexpr int WM   = BM / WARPS_M;
    constexpr int WN   = BN / WARPS_N;
    constexpr int MI   = WM / 16;
    constexpr int NI   = WN / 8;
    constexpr int ASTR = BK + 4;
    constexpr int BSTR = BN + 8;

    __shared__ __align__(16) float As[2][BM][ASTR];
    __shared__ __align__(16) float Bs[2][BK][BSTR];
    __shared__ float red[2][BM][WARPS_N];

    const int t    = threadIdx.x;
    const int lane = t & 31;
    const int warp = t >> 5;
    const int wm   = warp % WARPS_M;
    const int wn   = warp / WARPS_M;
    const int g    = lane >> 2;
    const int c    = lane & 3;
    const int m0   = blockIdx.y * BM;
    const int n0   = FUSE_LN ? 0 : blockIdx.x * BN;

    const int a_row = t >> 2;
    const int a_ch  = (t & 3) * 4;
    constexpr int B_CHUNKS = (BK * BN / 4) / 256;

    float acc[MI][NI][4];
#pragma unroll
    for (int mI = 0; mI < MI; ++mI)
#pragma unroll
        for (int nI = 0; nI < NI; ++nI)
#pragma unroll
            for (int r = 0; r < 4; ++r) acc[mI][nI][r] = 0.f;

    auto issue_tile = [&](int kt, int buf) {
        const int k0 = kt * BK;
        {
            const int gm = m0 + a_row;
            const bool ok = gm < M;
            const float* src = A + (ok ? ((size_t)gm * K + k0 + a_ch) : 0);
            cp16(&As[buf][a_row][a_ch], src, ok ? 16 : 0);
        }
#pragma unroll
        for (int i = 0; i < B_CHUNKS; ++i) {
            const int s  = t + i * 256;
            const int bk = s / (BN / 4);
            const int bn = (s % (BN / 4)) * 4;
            const bool ok = (!PRED_N || (n0 + bn) < N);
            const float* src = W + (ok ? ((size_t)(k0 + bk) * N + n0 + bn) : 0);
            cp16(&Bs[buf][bk][bn], src, ok ? 16 : 0);
        }
        asm volatile("cp.async.commit_group;" ::: "memory");
    };

    const int kTiles = K / BK;
    issue_tile(0, 0);

    for (int kt = 0; kt < kTiles; ++kt) {
        asm volatile("cp.async.wait_group 0;" ::: "memory");
        __syncthreads();
        if (kt + 1 < kTiles) issue_tile(kt + 1, (kt + 1) & 1);
        const int buf = kt & 1;
#pragma unroll
        for (int ks = 0; ks < 2; ++ks) {
            const int kb = ks * 8;
            uint32_t af[MI][4], bf[NI][2];
#pragma unroll
            for (int mI = 0; mI < MI; ++mI) {
                const int row = wm * WM + mI * 16;
                af[mI][0] = __float_as_uint(As[buf][row + g    ][kb + c    ]);
                af[mI][1] = __float_as_uint(As[buf][row + g + 8][kb + c    ]);
                af[mI][2] = __float_as_uint(As[buf][row + g    ][kb + c + 4]);
                af[mI][3] = __float_as_uint(As[buf][row + g + 8][kb + c + 4]);
            }
#pragma unroll
            for (int nI = 0; nI < NI; ++nI) {
                const int col = wn * WN + nI * 8 + g;
                bf[nI][0] = __float_as_uint(Bs[buf][kb + c    ][col]);
                bf[nI][1] = __float_as_uint(Bs[buf][kb + c + 4][col]);
            }
#pragma unroll
            for (int mI = 0; mI < MI; ++mI)
#pragma unroll
                for (int nI = 0; nI < NI; ++nI) {
                    float* d = acc[mI][nI];
                    asm volatile(
                        "mma.sync.aligned.m16n8k8.row.col.f32.tf32.tf32.f32 "
                        "{%0,%1,%2,%3}, {%4,%5,%6,%7}, {%8,%9}, {%0,%1,%2,%3};"
                        : "+f"(d[0]), "+f"(d[1]), "+f"(d[2]), "+f"(d[3])
                        : "r"(af[mI][0]), "r"(af[mI][1]),
                          "r"(af[mI][2]), "r"(af[mI][3]),
                          "r"(bf[nI][0]), "r"(bf[nI][1]));
                }
        }
    }

    // ---- bias ----
#pragma unroll
    for (int nI = 0; nI < NI; ++nI) {
        const int col = n0 + wn * WN + nI * 8 + 2 * c;
        float b0 = 0.f, b1 = 0.f;
        if (!PRED_N || col < N) { b0 = bias[col]; b1 = bias[col + 1]; }
#pragma unroll
        for (int mI = 0; mI < MI; ++mI) {
            acc[mI][nI][0] += b0; acc[mI][nI][1] += b1;
            acc[mI][nI][2] += b0; acc[mI][nI][3] += b1;
        }
    }

    float mean_[MI][2], rstd_[MI][2];
    if (FUSE_LN) {
#pragma unroll
        for (int mI = 0; mI < MI; ++mI)
#pragma unroll
            for (int h = 0; h < 2; ++h) {
                float s = 0.f, s2 = 0.f;
#pragma unroll
                for (int nI = 0; nI < NI; ++nI) {
                    const float v0 = acc[mI][nI][2 * h];
                    const float v1 = acc[mI][nI][2 * h + 1];
                    s += v0 + v1; s2 += v0 * v0 + v1 * v1;
                }
                s  += __shfl_xor_sync(0xffffffffu, s, 1);
                s  += __shfl_xor_sync(0xffffffffu, s, 2);
                s2 += __shfl_xor_sync(0xffffffffu, s2, 1);
                s2 += __shfl_xor_sync(0xffffffffu, s2, 2);
                if (c == 0) {
                    const int lr = wm * WM + mI * 16 + h * 8 + g;
                    red[0][lr][wn] = s;
                    red[1][lr][wn] = s2;
                }
            }
        __syncthreads();
#pragma unroll
        for (int mI = 0; mI < MI; ++mI)
#pragma unroll
            for (int h = 0; h < 2; ++h) {
                const int lr = wm * WM + mI * 16 + h * 8 + g;
                float s = 0.f, s2 = 0.f;
#pragma unroll
                for (int w = 0; w < WARPS_N; ++w) { s += red[0][lr][w]; s2 += red[1][lr][w]; }
                const float mean = s / (float)N;
                const float var  = s2 / (float)N - mean * mean;
                mean_[mI][h] = mean;
                rstd_[mI][h] = rsqrtf(var + 1e-5f);
            }
    }

#pragma unroll
    for (int nI = 0; nI < NI; ++nI) {
        const int col = n0 + wn * WN + nI * 8 + 2 * c;
        if (PRED_N && col >= N) continue;
        float ga0 = 0.f, ga1 = 0.f, be0 = 0.f, be1 = 0.f;
        if (FUSE_LN) { ga0 = gamma[col]; ga1 = gamma[col + 1];
                       be0 = beta[col];  be1 = beta[col + 1]; }
#pragma unroll
        for (int mI = 0; mI < MI; ++mI)
#pragma unroll
            for (int h = 0; h < 2; ++h) {
                const int m = m0 + wm * WM + mI * 16 + h * 8 + g;
                if (m >= M) continue;
                float v0 = acc[mI][nI][2 * h];
                float v1 = acc[mI][nI][2 * h + 1];
                if (FUSE_LN) {
                    v0 = (v0 - mean_[mI][h]) * rstd_[mI][h] * ga0 + be0;
                    v1 = (v1 - mean_[mI][h]) * rstd_[mI][h] * ga1 + be1;
                    v0 = v0 / (1.f + __expf(-v0));
                    v1 = v1 / (1.f + __expf(-v1));
                }
                float2 o = make_float2(v0, v1);
                *reinterpret_cast<float2*>(&C[(size_t)m * N + col]) = o;
            }
    }
}

// ---------------------------------------------------------------------------
// gemm3 + structure-factor epilogue. BM=64, BN=64, 256 thr, WARPS_M=4,
// WARPS_N=2 (WM=16 -> MI=1, WN=32 -> NI=4). N=300 (PRED), K=128.
// ff = A@W + bias computed in registers; per-row power tables of
// e^{i*2pi*p} (hkl components are integers in [-5,5]); complex products
// give cos/sin of the phase; block-reduced and atomically added to sf.
// ---------------------------------------------------------------------------
__global__ __launch_bounds__(256, 2) void tf32_gemm_sf(
    const float* __restrict__ A, const float* __restrict__ W,
    const float* __restrict__ bias,
    const float* __restrict__ pos, const int* __restrict__ batch,
    const float* __restrict__ hkl, float* __restrict__ sf,
    int M, int N, int K)
{
    constexpr int BM = 64, BN = 64, BK = 16;
    constexpr int WARPS_M = 4;
    constexpr int WM = 16, WN = 32, NI = 4;
    constexpr int ASTR = BK + 4;
    constexpr int BSTR = BN + 8;

    __shared__ __align__(16) float As[2][BM][ASTR];
    __shared__ __align__(16) float Bs[2][BK][BSTR];
    __shared__ float tab[BM][3][12];   // (re,im) of e^{i*2pi*p*a}, a=0..5
    __shared__ int   sb[BM];
    __shared__ int   ihkl[BN][3];
    __shared__ float buf[BN][2];

    const int t    = threadIdx.x;
    const int lane = t & 31;
    const int warp = t >> 5;
    const int wm   = warp % WARPS_M;
    const int wn   = warp / WARPS_M;
    const int g    = lane >> 2;
    const int c    = lane & 3;
    const int m0   = blockIdx.y * BM;
    const int n0   = blockIdx.x * BN;

    const int a_row = t >> 2;
    const int a_ch  = (t & 3) * 4;

    float acc[NI][4];
#pragma unroll
    for (int nI = 0; nI < NI; ++nI)
#pragma unroll
        for (int r = 0; r < 4; ++r) acc[nI][r] = 0.f;

    auto issue_tile = [&](int kt, int buf_i) {
        const int k0 = kt * BK;
        {
            const int gm = m0 + a_row;
            const bool ok = gm < M;
            const float* src = A + (ok ? ((size_t)gm * K + k0 + a_ch) : 0);
            cp16(&As[buf_i][a_row][a_ch], src, ok ? 16 : 0);
        }
        {
            const int bk = t / (BN / 4);
            const int bn = (t % (BN / 4)) * 4;
            const bool ok = (n0 + bn) < N;
            const float* src = W + (ok ? ((size_t)(k0 + bk) * N + n0 + bn) : 0);
            cp16(&Bs[buf_i][bk][bn], src, ok ? 16 : 0);
        }
        asm volatile("cp.async.commit_group;" ::: "memory");
    };

    const int kTiles = K / BK;
    issue_tile(0, 0);

    for (int kt = 0; kt < kTiles; ++kt) {
        asm volatile("cp.async.wait_group 0;" ::: "memory");
        __syncthreads();
        if (kt + 1 < kTiles) issue_tile(kt + 1, (kt + 1) & 1);
        const int bi = kt & 1;
#pragma unroll
        for (int ks = 0; ks < 2; ++ks) {
            const int kb = ks * 8;
            uint32_t af[4], bf[NI][2];
            {
                const int row = wm * WM;
                af[0] = __float_as_uint(As[bi][row + g    ][kb + c    ]);
                af[1] = __float_as_uint(As[bi][row + g + 8][kb + c    ]);
                af[2] = __float_as_uint(As[bi][row + g    ][kb + c + 4]);
                af[3] = __float_as_uint(As[bi][row + g + 8][kb + c + 4]);
            }
#pragma unroll
            for (int nI = 0; nI < NI; ++nI) {
                const int col = wn * WN + nI * 8 + g;
                bf[nI][0] = __float_as_uint(Bs[bi][kb + c    ][col]);
                bf[nI][1] = __float_as_uint(Bs[bi][kb + c + 4][col]);
            }
#pragma unroll
            for (int nI = 0; nI < NI; ++nI) {
                float* d = acc[nI];
                asm volatile(
                    "mma.sync.aligned.m16n8k8.row.col.f32.tf32.tf32.f32 "
                    "{%0,%1,%2,%3}, {%4,%5,%6,%7}, {%8,%9}, {%0,%1,%2,%3};"
                    : "+f"(d[0]), "+f"(d[1]), "+f"(d[2]), "+f"(d[3])
                    : "r"(af[0]), "r"(af[1]), "r"(af[2]), "r"(af[3]),
                      "r"(bf[nI][0]), "r"(bf[nI][1]));
            }
        }
    }

    // ---- bias ----
#pragma unroll
    for (int nI = 0; nI < NI; ++nI) {
        const int col = n0 + wn * WN + nI * 8 + 2 * c;
        float b0 = 0.f, b1 = 0.f;
        if (col < N) { b0 = bias[col]; b1 = bias[col + 1]; }
        acc[nI][0] += b0; acc[nI][1] += b1;
        acc[nI][2] += b0; acc[nI][3] += b1;
    }

    // ---- build per-row power tables, batch ids, integer hkl ----
    if (t < BM) sb[t] = batch[min(m0 + t, M - 1)];
    if (t < BM * 3) {
        const int r = t / 3, ax = t % 3;
        const int gm = m0 + r;
        const float p = (gm < M) ? pos[gm * 3 + ax] : 0.f;
        const float ang = 6.283185307179586f * (p - rintf(p));
        float s1, c1;
        __sincosf(ang, &s1, &c1);
        tab[r][ax][0] = 1.f; tab[r][ax][1] = 0.f;
        float cr = 1.f, ci = 0.f;
#pragma unroll
        for (int a = 1; a <= 5; ++a) {
            const float nr = cr * c1 - ci * s1;
            const float ni = ci * c1 + cr * s1;
            cr = nr; ci = ni;
            tab[r][ax][2 * a]     = cr;
            tab[r][ax][2 * a + 1] = ci;
        }
    }
    if (t < BN * 3) {
        const int jj = t / 3, ax = t % 3;
        const int j = n0 + jj;
        ihkl[jj][ax] = (j < N) ? __float2int_rn(hkl[j * 3 + ax]) : 0;
    }
    __syncthreads();

    // ---- per-element f*cos, f*sin ----
    float fre[2][NI][2], fim[2][NI][2];
#pragma unroll
    for (int h = 0; h < 2; ++h) {
        const int ml = wm * WM + h * 8 + g;
        const bool mok = (m0 + ml) < M;
#pragma unroll
        for (int nI = 0; nI < NI; ++nI)
#pragma unroll
            for (int q = 0; q < 2; ++q) {
                const int jj = wn * WN + nI * 8 + 2 * c + q;
                const int j  = n0 + jj;
                if (!mok || j >= N) { fre[h][nI][q] = 0.f; fim[h][nI][q] = 0.f; continue; }
                const float f = acc[nI][h * 2 + q];
                const int ih = ihkl[jj][0], ik = ihkl[jj][1], il = ihkl[jj][2];
                const int ah = abs(ih), ak = abs(ik), al = abs(il);
                float xr = tab[ml][0][2 * ah], xi = tab[ml][0][2 * ah + 1];
                if (ih < 0) xi = -xi;
                float yr = tab[ml][1][2 * ak], yi = tab[ml][1][2 * ak + 1];
                if (ik < 0) yi = -yi;
                float zr = tab[ml][2][2 * al], zi = tab[ml][2][2 * al + 1];
                if (il < 0) zi = -zi;
                const float ur = xr * yr - xi * yi;
                const float ui = xr * yi + xi * yr;
                const float vr = ur * zr - ui * zi;
                const float vi = ur * zi + ui * zr;
                fre[h][nI][q] = f * vr;
                fim[h][nI][q] = f * vi;
            }
    }

    // ---- reduce over rows per batch id and add to sf ----
    const int b_lo = sb[0], b_hi = sb[BM - 1];
    const int bm0 = sb[wm * WM + g];
    const int bm1 = sb[wm * WM + 8 + g];

    for (int b = b_lo; b <= b_hi; ++b) {
        for (int i = t; i < BN * 2; i += 256) ((float*)buf)[i] = 0.f;
        __syncthreads();
#pragma unroll
        for (int nI = 0; nI < NI; ++nI)
#pragma unroll
            for (int q = 0; q < 2; ++q) {
                float sre = (bm0 == b ? fre[0][nI][q] : 0.f)
                          + (bm1 == b ? fre[1][nI][q] : 0.f);
                float sim = (bm0 == b ? fim[0][nI][q] : 0.f)
                          + (bm1 == b ? fim[1][nI][q] : 0.f);
#pragma unroll
                for (int off = 4; off <= 16; off <<= 1) {
                    sre += __shfl_xor_sync(0xffffffffu, sre, off);
                    sim += __shfl_xor_sync(0xffffffffu, sim, off);
                }
                if (g == 0) {
                    const int jj = wn * WN + nI * 8 + 2 * c + q;
                    atomicAdd(&buf[jj][0], sre);
                    atomicAdd(&buf[jj][1], sim);
                }
            }
        __syncthreads();
        for (int i = t; i < BN; i += 256) {
            const int j = n0 + i;
            if (j < N) {
                const float br = buf[i][0], bi2 = buf[i][1];
                if (br != 0.f) atomicAdd(&sf[b * 600 + 2 * j + 0], br);
                if (bi2 != 0.f) atomicAdd(&sf[b * 600 + 2 * j + 1], bi2);
            }
        }
        __syncthreads();
    }
}

// ---------------------------------------------------------------------------
// Small SGEMM (B=256 rows): 64x64, BK=16, 4x4 microtile.
// ---------------------------------------------------------------------------
__global__ __launch_bounds__(256) void sgemm_small(
    const float* __restrict__ A, const float* __restrict__ W,
    const float* __restrict__ bias, const float* __restrict__ residual,
    float* __restrict__ C, int M, int N, int K)
{
    __shared__ float As[16][64];
    __shared__ float Bs[16][68];

    const int t  = threadIdx.x;
    const int tx = t & 15;
    const int ty = t >> 4;
    const int n0 = blockIdx.x * 64;
    const int m0 = blockIdx.y * 64;

    float acc[4][4];
#pragma unroll
    for (int i = 0; i < 4; ++i)
#pragma unroll
        for (int j = 0; j < 4; ++j) acc[i][j] = 0.f;

    const int kTiles = (K + 15) / 16;
    for (int kt = 0; kt < kTiles; ++kt) {
        const int k0 = kt * 16;
        {
            const int row = t >> 2;
            const int c4  = (t & 3) * 4;
            const int gm = m0 + row, gk = k0 + c4;
            float4 v = make_float4(0.f,0.f,0.f,0.f);
            if (gm < M && gk < K)
                v = *reinterpret_cast<const float4*>(&A[(size_t)gm * K + gk]);
            As[c4 + 0][row] = v.x; As[c4 + 1][row] = v.y;
            As[c4 + 2][row] = v.z; As[c4 + 3][row] = v.w;
        }
        {
            const int rowk = t >> 4;
            const int c4   = (t & 15) * 4;
            const int gk = k0 + rowk, gn = n0 + c4;
            float4 v = make_float4(0.f,0.f,0.f,0.f);
            if (gk < K && gn < N)
                v = *reinterpret_cast<const float4*>(&W[(size_t)gk * N + gn]);
            *reinterpret_cast<float4*>(&Bs[rowk][c4]) = v;
        }
        __syncthreads();

#pragma unroll
        for (int kk = 0; kk < 16; ++kk) {
            float4 av = *reinterpret_cast<const float4*>(&As[kk][ty * 4]);
            float4 bv = *reinterpret_cast<const float4*>(&Bs[kk][tx * 4]);
            float a[4] = {av.x,av.y,av.z,av.w};
            float b[4] = {bv.x,bv.y,bv.z,bv.w};
#pragma unroll
            for (int i = 0; i < 4; ++i)
#pragma unroll
                for (int j = 0; j < 4; ++j)
                    acc[i][j] = fmaf(a[i], b[j], acc[i][j]);
        }
        __syncthreads();
    }

#pragma unroll
    for (int i = 0; i < 4; ++i) {
        const int m = m0 + ty * 4 + i;
        if (m >= M) continue;
#pragma unroll
        for (int j = 0; j < 4; ++j) {
            const int n = n0 + tx * 4 + j;
            if (n >= N) continue;
            float v = acc[i][j] + bias[n];
            if (residual) v += residual[(size_t)m * N + n];
            C[(size_t)m * N + n] = v;
        }
    }
}

// ---------------------------------------------------------------------------
__global__ void ln_silu_kernel(float* __restrict__ X, const float* __restrict__ g,
                               const float* __restrict__ b, int W, int do_silu)
{
    const int row = blockIdx.x;
    const int t = threadIdx.x;
    const int lane = t & 31, warp = t >> 5, nw = W >> 5;
    __shared__ float red[16];

    float x = X[(size_t)row * W + t];

    float s = x;
#pragma unroll
    for (int o = 16; o > 0; o >>= 1) s += __shfl_xor_sync(0xffffffffu, s, o);
    if (lane == 0) red[warp] = s;
    __syncthreads();
    float v = (lane < nw) ? red[lane] : 0.f;
#pragma unroll
    for (int o = 16; o > 0; o >>= 1) v += __shfl_xor_sync(0xffffffffu, v, o);
    const float mean = v / (float)W;
    __syncthreads();

    const float dx = x - mean;
    float s2 = dx * dx;
#pragma unroll
    for (int o = 16; o > 0; o >>= 1) s2 += __shfl_xor_sync(0xffffffffu, s2, o);
    if (lane == 0) red[warp] = s2;
    __syncthreads();
    float v2 = (lane < nw) ? red[lane] : 0.f;
#pragma unroll
    for (int o = 16; o > 0; o >>= 1) v2 += __shfl_xor_sync(0xffffffffu, v2, o);
    const float var = v2 / (float)W;

    float y = dx * rsqrtf(var + 1e-5f) * g[t] + b[t];
    if (do_silu) y = y * (1.0f / (1.0f + expf(-y)));
    X[(size_t)row * W + t] = y;
}

// ---------------------------------------------------------------------------
__global__ void zero_kernel(float* __restrict__ p, int n)
{
    int i = threadIdx.x + blockIdx.x * blockDim.x;
    if (i < n) p[i] = 0.f;
}

// ---------------------------------------------------------------------------
__global__ void concat_kernel(const float* __restrict__ a,
                              const float* __restrict__ b,
                              float* __restrict__ out, int Wa, int Wb)
{
    const int row = blockIdx.x;
    for (int t = threadIdx.x; t < Wa + Wb; t += blockDim.x) {
        float v = (t < Wa) ? a[(size_t)row * Wa + t] : b[(size_t)row * Wb + (t - Wa)];
        out[(size_t)row * (Wa + Wb) + t] = v;
    }
}

// ---------------------------------------------------------------------------
extern "C" void kernel_launch(void* const* d_in, const int* in_sizes, int n_in,
                              void* d_out, int out_size)
{
    const float* graph  = (const float*)d_in[0];
    const float* nodef  = (const float*)d_in[1];
    const float* pos    = (const float*)d_in[2];
    const int*   batch  = (const int*)  d_in[3];
    const float* hkl    = (const float*)d_in[4];
    const float* ff_w1  = (const float*)d_in[5];
    const float* ff_b1  = (const float*)d_in[6];
    const float* ff_g1  = (const float*)d_in[7];
    const float* ff_bb1 = (const float*)d_in[8];
    const float* ff_w2  = (const float*)d_in[9];
    const float* ff_b2  = (const float*)d_in[10];
    const float* ff_g2  = (const float*)d_in[11];
    const float* ff_bb2 = (const float*)d_in[12];
    const float* ff_w3  = (const float*)d_in[13];
    const float* ff_b3  = (const float*)d_in[14];
    const float* dn_w1  = (const float*)d_in[15];
    const float* dn_b1  = (const float*)d_in[16];
    const float* dn_g1  = (const float*)d_in[17];
    const float* dn_bb1 = (const float*)d_in[18];
    const float* dn_w2  = (const float*)d_in[19];
    const float* dn_b2  = (const float*)d_in[20];
    const float* dn_g2  = (const float*)d_in[21];
    const float* dn_bb2 = (const float*)d_in[22];
    const float* dn_w3  = (const float*)d_in[23];
    const float* dn_b3  = (const float*)d_in[24];
    const float* fn_w1  = (const float*)d_in[25];
    const float* fn_b1  = (const float*)d_in[26];
    const float* fn_g   = (const float*)d_in[27];
    const float* fn_bb  = (const float*)d_in[28];
    const float* fn_w2  = (const float*)d_in[29];
    const float* fn_b2  = (const float*)d_in[30];
    float* out = (float*)d_out;

    const int N = in_sizes[3];
    const int B = in_sizes[0] / 512;

    float *s1, *s2, *sf, *dd1, *dd2, *dd3, *comb, *f1;
    cudaGetSymbolAddress((void**)&s1,   g_s1);
    cudaGetSymbolAddress((void**)&s2,   g_s2);
    cudaGetSymbolAddress((void**)&sf,   g_sf);
    cudaGetSymbolAddress((void**)&dd1,  g_d1);
    cudaGetSymbolAddress((void**)&dd2,  g_d2);
    cudaGetSymbolAddress((void**)&dd3,  g_d3);
    cudaGetSymbolAddress((void**)&comb, g_comb);
    cudaGetSymbolAddress((void**)&f1,   g_f1);

    const int gy = (N + 63) / 64;

    // zero sf first (consumed by gemm3's fused epilogue atomics)
    zero_kernel<<<(B * 600 + 255) / 256, 256>>>(sf, B * 600);

    // --- node MLP ---
    tf32_gemm<64, 256, 2, 4, true,  false><<<dim3(1, gy), 256>>>(
        nodef, ff_w1, ff_b1, ff_g1, ff_bb1, s1, N, 256, 256);
    tf32_gemm<64, 128, 4, 2, true,  false><<<dim3(1, gy), 256>>>(
        s1, ff_w2, ff_b2, ff_g2, ff_bb2, s2, N, 128, 256);

    // --- gemm3 + structure factors fused ---
    tf32_gemm_sf<<<dim3(5, gy), 256>>>(
        s2, ff_w3, ff_b3, pos, batch, hkl, sf, N, 300, 128);

    // --- diffraction net (B rows) ---
    sgemm_small<<<dim3(8, (B + 63) / 64), 256>>>(sf, dn_w1, dn_b1, nullptr, dd1, B, 512, 600);
    ln_silu_kernel<<<B, 512>>>(dd1, dn_g1, dn_bb1, 512, 1);
    sgemm_small<<<dim3(4, (B + 63) / 64), 256>>>(dd1, dn_w2, dn_b2, nullptr, dd2, B, 256, 512);
    ln_silu_kernel<<<B, 256>>>(dd2, dn_g2, dn_bb2, 256, 1);
    sgemm_small<<<dim3(8, (B + 63) / 64), 256>>>(dd2, dn_w3, dn_b3, nullptr, dd3, B, 512, 256);

    // --- fusion net + residual ---
    concat_kernel<<<B, 256>>>(graph, dd3, comb, 512, 512);
    sgemm_small<<<dim3(8, (B + 63) / 64), 256>>>(comb, fn_w1, fn_b1, nullptr, f1, B, 512, 1024);
    ln_silu_kernel<<<B, 512>>>(f1, fn_g, fn_bb, 512, 1);
    sgemm_small<<<dim3(8, (B + 63) / 64), 256>>>(f1, fn_w2, fn_b2, graph, out, B, 512, 512);
}

// round 7
// speedup vs baseline: 1.1499x; 1.1499x over previous
#include <cuda_runtime.h>
#include <cuda_bf16.h>
#include <math.h>
#include <stdint.h>

// ---------------------------------------------------------------------------
// DiffractionIntegration — v6
//   Tall GEMMs: bf16 mma.m16n8k16 (fp32 accumulate), fused LN/SiLU epilogues,
//   weights pre-transposed to [n][k] bf16, activations carried in bf16.
//   Structure factors: split accum kernel (v4 path — proven faster than fused).
//   Small-batch chain: fp32 (unchanged).
// ---------------------------------------------------------------------------

#define NNODE_MAX 200000
#define BMAX      256

__device__ __nv_bfloat16 g_nf [(size_t)NNODE_MAX * 256];  // nodef bf16
__device__ __nv_bfloat16 g_s1b[(size_t)NNODE_MAX * 256];  // act1 bf16
__device__ __nv_bfloat16 g_s2b[(size_t)NNODE_MAX * 128];  // act2 bf16
__device__ __nv_bfloat16 g_wt1[256 * 256];                // ff_w1^T bf16 [n][k]
__device__ __nv_bfloat16 g_wt2[128 * 256];                // ff_w2^T
__device__ __nv_bfloat16 g_wt3[300 * 128];                // ff_w3^T
__device__ float g_ff[(size_t)NNODE_MAX * 300];
__device__ float g_sf[BMAX * 600];
__device__ float g_d1[BMAX * 512];
__device__ float g_d2[BMAX * 256];
__device__ float g_d3[BMAX * 512];
__device__ float g_comb[BMAX * 1024];
__device__ float g_f1[BMAX * 512];
__device__ int   g_seg[BMAX + 1];

// ---------------------------------------------------------------------------
__device__ __forceinline__ void cp16(void* dst_smem, const void* src, int bytes)
{
    uint32_t d = (uint32_t)__cvta_generic_to_shared(dst_smem);
    asm volatile("cp.async.cg.shared.global [%0], [%1], 16, %2;"
                 :: "r"(d), "l"(src), "r"(bytes) : "memory");
}

// ---------------------------------------------------------------------------
// bf16 GEMM: C[M,N] = A[M,K] @ Wt[N,K]^T + bias, optional fused LN+SiLU
// (BN == N, gridDim.x == 1). A row-major bf16; Wt row-major [n][k] bf16.
// BM=64, BK=16, 256 threads, mma.m16n8k16 bf16 -> fp32.
// ---------------------------------------------------------------------------
template<int BM, int BN, int WARPS_M, int WARPS_N, bool FUSE_LN, bool PRED_N,
         bool OUT_BF16>
__global__ __launch_bounds__(256, 2) void bf16_gemm(
    const __nv_bfloat16* __restrict__ A, const __nv_bfloat16* __restrict__ Wt,
    const float* __restrict__ bias, const float* __restrict__ gamma,
    const float* __restrict__ beta, void* __restrict__ Cout,
    int M, int N, int K)
{
    constexpr int BK   = 16;
    constexpr int WM   = BM / WARPS_M;
    constexpr int WN   = BN / WARPS_N;
    constexpr int MI   = WM / 16;
    constexpr int NI   = WN / 8;
    constexpr int ASTR = BK + 8;   // bf16 units; 24 -> 12 words: conflict-free
    constexpr int BSTR = BK + 8;

    __shared__ __align__(16) __nv_bfloat16 As[2][BM][ASTR];
    __shared__ __align__(16) __nv_bfloat16 Bs[2][BN][BSTR];
    __shared__ float red[2][BM][WARPS_N];

    const int t    = threadIdx.x;
    const int lane = t & 31;
    const int warp = t >> 5;
    const int wm   = warp % WARPS_M;
    const int wn   = warp / WARPS_M;
    const int g    = lane >> 2;
    const int c    = lane & 3;
    const int m0   = blockIdx.y * BM;
    const int n0   = FUSE_LN ? 0 : blockIdx.x * BN;

    float acc[MI][NI][4];
#pragma unroll
    for (int mI = 0; mI < MI; ++mI)
#pragma unroll
        for (int nI = 0; nI < NI; ++nI)
#pragma unroll
            for (int r = 0; r < 4; ++r) acc[mI][nI][r] = 0.f;

    // copy mappings: 16B chunk = 8 bf16; each row of a tile = 2 chunks (BK=16)
    auto issue_tile = [&](int kt, int buf) {
        const int k0 = kt * BK;
        if (t < BM * 2) {                     // A tile: BM rows x 2 chunks
            const int row = t >> 1;
            const int kc  = (t & 1) * 8;
            const int gm = m0 + row;
            const bool ok = gm < M;
            const __nv_bfloat16* src = A + (ok ? ((size_t)gm * K + k0 + kc) : 0);
            cp16(&As[buf][row][kc], src, ok ? 16 : 0);
        }
#pragma unroll
        for (int i = 0; i < (BN * 2 + 255) / 256; ++i) {  // B tile: BN rows x 2
            const int s = t + i * 256;
            if (s < BN * 2) {
                const int row = s >> 1;
                const int kc  = (s & 1) * 8;
                const bool ok = (!PRED_N || (n0 + row) < N);
                const __nv_bfloat16* src =
                    Wt + (ok ? ((size_t)(n0 + row) * K + k0 + kc) : 0);
                cp16(&Bs[buf][row][kc], src, ok ? 16 : 0);
            }
        }
        asm volatile("cp.async.commit_group;" ::: "memory");
    };

    const int kTiles = K / BK;
    issue_tile(0, 0);

#pragma unroll 2
    for (int kt = 0; kt < kTiles; ++kt) {
        asm volatile("cp.async.wait_group 0;" ::: "memory");
        __syncthreads();
        if (kt + 1 < kTiles) issue_tile(kt + 1, (kt + 1) & 1);
        const int buf = kt & 1;

        uint32_t af[MI][4], bf[NI][2];
#pragma unroll
        for (int mI = 0; mI < MI; ++mI) {
            const int row = wm * WM + mI * 16;
            af[mI][0] = *(const uint32_t*)&As[buf][row + g    ][2 * c    ];
            af[mI][1] = *(const uint32_t*)&As[buf][row + g + 8][2 * c    ];
            af[mI][2] = *(const uint32_t*)&As[buf][row + g    ][2 * c + 8];
            af[mI][3] = *(const uint32_t*)&As[buf][row + g + 8][2 * c + 8];
        }
#pragma unroll
        for (int nI = 0; nI < NI; ++nI) {
            const int col = wn * WN + nI * 8 + g;
            bf[nI][0] = *(const uint32_t*)&Bs[buf][col][2 * c    ];
            bf[nI][1] = *(const uint32_t*)&Bs[buf][col][2 * c + 8];
        }
#pragma unroll
        for (int mI = 0; mI < MI; ++mI)
#pragma unroll
            for (int nI = 0; nI < NI; ++nI) {
                float* d = acc[mI][nI];
                asm volatile(
                    "mma.sync.aligned.m16n8k16.row.col.f32.bf16.bf16.f32 "
                    "{%0,%1,%2,%3}, {%4,%5,%6,%7}, {%8,%9}, {%0,%1,%2,%3};"
                    : "+f"(d[0]), "+f"(d[1]), "+f"(d[2]), "+f"(d[3])
                    : "r"(af[mI][0]), "r"(af[mI][1]),
                      "r"(af[mI][2]), "r"(af[mI][3]),
                      "r"(bf[nI][0]), "r"(bf[nI][1]));
            }
    }

    // ---- bias ----
#pragma unroll
    for (int nI = 0; nI < NI; ++nI) {
        const int col = n0 + wn * WN + nI * 8 + 2 * c;
        float b0 = 0.f, b1 = 0.f;
        if (!PRED_N || col < N) { b0 = bias[col]; b1 = bias[col + 1]; }
#pragma unroll
        for (int mI = 0; mI < MI; ++mI) {
            acc[mI][nI][0] += b0; acc[mI][nI][1] += b1;
            acc[mI][nI][2] += b0; acc[mI][nI][3] += b1;
        }
    }

    float mean_[MI][2], rstd_[MI][2];
    if (FUSE_LN) {
#pragma unroll
        for (int mI = 0; mI < MI; ++mI)
#pragma unroll
            for (int h = 0; h < 2; ++h) {
                float s = 0.f, s2 = 0.f;
#pragma unroll
                for (int nI = 0; nI < NI; ++nI) {
                    const float v0 = acc[mI][nI][2 * h];
                    const float v1 = acc[mI][nI][2 * h + 1];
                    s += v0 + v1; s2 += v0 * v0 + v1 * v1;
                }
                s  += __shfl_xor_sync(0xffffffffu, s, 1);
                s  += __shfl_xor_sync(0xffffffffu, s, 2);
                s2 += __shfl_xor_sync(0xffffffffu, s2, 1);
                s2 += __shfl_xor_sync(0xffffffffu, s2, 2);
                if (c == 0) {
                    const int lr = wm * WM + mI * 16 + h * 8 + g;
                    red[0][lr][wn] = s;
                    red[1][lr][wn] = s2;
                }
            }
        __syncthreads();
#pragma unroll
        for (int mI = 0; mI < MI; ++mI)
#pragma unroll
            for (int h = 0; h < 2; ++h) {
                const int lr = wm * WM + mI * 16 + h * 8 + g;
                float s = 0.f, s2 = 0.f;
#pragma unroll
                for (int w = 0; w < WARPS_N; ++w) { s += red[0][lr][w]; s2 += red[1][lr][w]; }
                const float mean = s / (float)N;
                const float var  = s2 / (float)N - mean * mean;
                mean_[mI][h] = mean;
                rstd_[mI][h] = rsqrtf(var + 1e-5f);
            }
    }

    // ---- store ----
#pragma unroll
    for (int nI = 0; nI < NI; ++nI) {
        const int col = n0 + wn * WN + nI * 8 + 2 * c;
        if (PRED_N && col >= N) continue;
        float ga0 = 0.f, ga1 = 0.f, be0 = 0.f, be1 = 0.f;
        if (FUSE_LN) { ga0 = gamma[col]; ga1 = gamma[col + 1];
                       be0 = beta[col];  be1 = beta[col + 1]; }
#pragma unroll
        for (int mI = 0; mI < MI; ++mI)
#pragma unroll
            for (int h = 0; h < 2; ++h) {
                const int m = m0 + wm * WM + mI * 16 + h * 8 + g;
                if (m >= M) continue;
                float v0 = acc[mI][nI][2 * h];
                float v1 = acc[mI][nI][2 * h + 1];
                if (FUSE_LN) {
                    v0 = (v0 - mean_[mI][h]) * rstd_[mI][h] * ga0 + be0;
                    v1 = (v1 - mean_[mI][h]) * rstd_[mI][h] * ga1 + be1;
                    v0 = v0 / (1.f + __expf(-v0));
                    v1 = v1 / (1.f + __expf(-v1));
                }
                if (OUT_BF16) {
                    __nv_bfloat162 o = __floats2bfloat162_rn(v0, v1);
                    *reinterpret_cast<__nv_bfloat162*>(
                        &((__nv_bfloat16*)Cout)[(size_t)m * N + col]) = o;
                } else {
                    *reinterpret_cast<float2*>(
                        &((float*)Cout)[(size_t)m * N + col]) = make_float2(v0, v1);
                }
            }
    }
}

// ---------------------------------------------------------------------------
// Conversions (one-time prologue)
// ---------------------------------------------------------------------------
__global__ void f32_to_bf16_kernel(const float* __restrict__ in,
                                   __nv_bfloat16* __restrict__ out, size_t n)
{
    const size_t i = ((size_t)blockIdx.x * blockDim.x + threadIdx.x) * 2;
    if (i < n) {
        float2 v = *reinterpret_cast<const float2*>(&in[i]);
        *reinterpret_cast<__nv_bfloat162*>(&out[i]) = __floats2bfloat162_rn(v.x, v.y);
    }
}

// W[K][N] f32 -> Wt[N][K] bf16 (small matrices; naive)
__global__ void conv_transpose_kernel(const float* __restrict__ w,
                                      __nv_bfloat16* __restrict__ wt,
                                      int K, int N)
{
    const int idx = blockIdx.x * blockDim.x + threadIdx.x;
    if (idx < K * N) {
        const int k = idx / N, n = idx % N;
        wt[(size_t)n * K + k] = __float2bfloat16(w[idx]);
    }
}

// ---------------------------------------------------------------------------
// Small SGEMM (B=256 rows): 64x64, BK=16, 4x4 microtile.
// ---------------------------------------------------------------------------
__global__ __launch_bounds__(256) void sgemm_small(
    const float* __restrict__ A, const float* __restrict__ W,
    const float* __restrict__ bias, const float* __restrict__ residual,
    float* __restrict__ C, int M, int N, int K)
{
    __shared__ float As[16][64];
    __shared__ float Bs[16][68];

    const int t  = threadIdx.x;
    const int tx = t & 15;
    const int ty = t >> 4;
    const int n0 = blockIdx.x * 64;
    const int m0 = blockIdx.y * 64;

    float acc[4][4];
#pragma unroll
    for (int i = 0; i < 4; ++i)
#pragma unroll
        for (int j = 0; j < 4; ++j) acc[i][j] = 0.f;

    const int kTiles = (K + 15) / 16;
    for (int kt = 0; kt < kTiles; ++kt) {
        const int k0 = kt * 16;
        {
            const int row = t >> 2;
            const int c4  = (t & 3) * 4;
            const int gm = m0 + row, gk = k0 + c4;
            float4 v = make_float4(0.f,0.f,0.f,0.f);
            if (gm < M && gk < K)
                v = *reinterpret_cast<const float4*>(&A[(size_t)gm * K + gk]);
            As[c4 + 0][row] = v.x; As[c4 + 1][row] = v.y;
            As[c4 + 2][row] = v.z; As[c4 + 3][row] = v.w;
        }
        {
            const int rowk = t >> 4;
            const int c4   = (t & 15) * 4;
            const int gk = k0 + rowk, gn = n0 + c4;
            float4 v = make_float4(0.f,0.f,0.f,0.f);
            if (gk < K && gn < N)
                v = *reinterpret_cast<const float4*>(&W[(size_t)gk * N + gn]);
            *reinterpret_cast<float4*>(&Bs[rowk][c4]) = v;
        }
        __syncthreads();

#pragma unroll
        for (int kk = 0; kk < 16; ++kk) {
            float4 av = *reinterpret_cast<const float4*>(&As[kk][ty * 4]);
            float4 bv = *reinterpret_cast<const float4*>(&Bs[kk][tx * 4]);
            float a[4] = {av.x,av.y,av.z,av.w};
            float b[4] = {bv.x,bv.y,bv.z,bv.w};
#pragma unroll
            for (int i = 0; i < 4; ++i)
#pragma unroll
                for (int j = 0; j < 4; ++j)
                    acc[i][j] = fmaf(a[i], b[j], acc[i][j]);
        }
        __syncthreads();
    }

#pragma unroll
    for (int i = 0; i < 4; ++i) {
        const int m = m0 + ty * 4 + i;
        if (m >= M) continue;
#pragma unroll
        for (int j = 0; j < 4; ++j) {
            const int n = n0 + tx * 4 + j;
            if (n >= N) continue;
            float v = acc[i][j] + bias[n];
            if (residual) v += residual[(size_t)m * N + n];
            C[(size_t)m * N + n] = v;
        }
    }
}

// ---------------------------------------------------------------------------
__global__ void ln_silu_kernel(float* __restrict__ X, const float* __restrict__ g,
                               const float* __restrict__ b, int W, int do_silu)
{
    const int row = blockIdx.x;
    const int t = threadIdx.x;
    const int lane = t & 31, warp = t >> 5, nw = W >> 5;
    __shared__ float red[16];

    float x = X[(size_t)row * W + t];

    float s = x;
#pragma unroll
    for (int o = 16; o > 0; o >>= 1) s += __shfl_xor_sync(0xffffffffu, s, o);
    if (lane == 0) red[warp] = s;
    __syncthreads();
    float v = (lane < nw) ? red[lane] : 0.f;
#pragma unroll
    for (int o = 16; o > 0; o >>= 1) v += __shfl_xor_sync(0xffffffffu, v, o);
    const float mean = v / (float)W;
    __syncthreads();

    const float dx = x - mean;
    float s2 = dx * dx;
#pragma unroll
    for (int o = 16; o > 0; o >>= 1) s2 += __shfl_xor_sync(0xffffffffu, s2, o);
    if (lane == 0) red[warp] = s2;
    __syncthreads();
    float v2 = (lane < nw) ? red[lane] : 0.f;
#pragma unroll
    for (int o = 16; o > 0; o >>= 1) v2 += __shfl_xor_sync(0xffffffffu, v2, o);
    const float var = v2 / (float)W;

    float y = dx * rsqrtf(var + 1e-5f) * g[t] + b[t];
    if (do_silu) y = y * (1.0f / (1.0f + expf(-y)));
    X[(size_t)row * W + t] = y;
}

// ---------------------------------------------------------------------------
__global__ void seg_kernel(const int* __restrict__ batch, int N, int B)
{
    const int b = threadIdx.x + blockIdx.x * blockDim.x;
    if (b > B) return;
    int lo = 0, hi = N;
    while (lo < hi) {
        int mid = (lo + hi) >> 1;
        if (batch[mid] < b) lo = mid + 1; else hi = mid;
    }
    g_seg[b] = lo;
}

__global__ void zero_kernel(float* __restrict__ p, int n)
{
    int i = threadIdx.x + blockIdx.x * blockDim.x;
    if (i < n) p[i] = 0.f;
}

// ---------------------------------------------------------------------------
// Structure-factor accumulation (v4 path). grid=(B, CHUNKS), 320 threads.
// ---------------------------------------------------------------------------
__global__ void accum_kernel(const float* __restrict__ ff,
                             const float* __restrict__ pos,
                             const float* __restrict__ hkl,
                             float* __restrict__ sf, int nchunks)
{
    const int b = blockIdx.x;
    const int chunk = blockIdx.y;
    const int j = threadIdx.x;
    if (j >= 300) return;

    const int s = g_seg[b], e = g_seg[b + 1];
    const int len = e - s;
    if (len <= 0) return;
    const int per = (len + nchunks - 1) / nchunks;
    const int n0 = s + chunk * per;
    const int n1 = (n0 + per < e) ? (n0 + per) : e;
    if (n0 >= e) return;

    const float hx = hkl[j * 3 + 0], hy = hkl[j * 3 + 1], hz = hkl[j * 3 + 2];
    float rj = 0.f, ij = 0.f;
    const float TWO_PI = 6.283185307179586f;

    for (int n = n0; n < n1; ++n) {
        const float px = __ldg(&pos[n * 3 + 0]);
        const float py = __ldg(&pos[n * 3 + 1]);
        const float pz = __ldg(&pos[n * 3 + 2]);
        const float f = ff[(size_t)n * 300 + j];
        float d = fmaf(px, hx, fmaf(py, hy, pz * hz));
        d -= rintf(d);
        float sn, cs;
        __sincosf(TWO_PI * d, &sn, &cs);
        rj = fmaf(f, cs, rj);
        ij = fmaf(f, sn, ij);
    }
    atomicAdd(&sf[b * 600 + 2 * j + 0], rj);
    atomicAdd(&sf[b * 600 + 2 * j + 1], ij);
}

// ---------------------------------------------------------------------------
__global__ void concat_kernel(const float* __restrict__ a,
                              const float* __restrict__ b,
                              float* __restrict__ out, int Wa, int Wb)
{
    const int row = blockIdx.x;
    for (int t = threadIdx.x; t < Wa + Wb; t += blockDim.x) {
        float v = (t < Wa) ? a[(size_t)row * Wa + t] : b[(size_t)row * Wb + (t - Wa)];
        out[(size_t)row * (Wa + Wb) + t] = v;
    }
}

// ---------------------------------------------------------------------------
extern "C" void kernel_launch(void* const* d_in, const int* in_sizes, int n_in,
                              void* d_out, int out_size)
{
    const float* graph  = (const float*)d_in[0];
    const float* nodef  = (const float*)d_in[1];
    const float* pos    = (const float*)d_in[2];
    const int*   batch  = (const int*)  d_in[3];
    const float* hkl    = (const float*)d_in[4];
    const float* ff_w1  = (const float*)d_in[5];
    const float* ff_b1  = (const float*)d_in[6];
    const float* ff_g1  = (const float*)d_in[7];
    const float* ff_bb1 = (const float*)d_in[8];
    const float* ff_w2  = (const float*)d_in[9];
    const float* ff_b2  = (const float*)d_in[10];
    const float* ff_g2  = (const float*)d_in[11];
    const float* ff_bb2 = (const float*)d_in[12];
    const float* ff_w3  = (const float*)d_in[13];
    const float* ff_b3  = (const float*)d_in[14];
    const float* dn_w1  = (const float*)d_in[15];
    const float* dn_b1  = (const float*)d_in[16];
    const float* dn_g1  = (const float*)d_in[17];
    const float* dn_bb1 = (const float*)d_in[18];
    const float* dn_w2  = (const float*)d_in[19];
    const float* dn_b2  = (const float*)d_in[20];
    const float* dn_g2  = (const float*)d_in[21];
    const float* dn_bb2 = (const float*)d_in[22];
    const float* dn_w3  = (const float*)d_in[23];
    const float* dn_b3  = (const float*)d_in[24];
    const float* fn_w1  = (const float*)d_in[25];
    const float* fn_b1  = (const float*)d_in[26];
    const float* fn_g   = (const float*)d_in[27];
    const float* fn_bb  = (const float*)d_in[28];
    const float* fn_w2  = (const float*)d_in[29];
    const float* fn_b2  = (const float*)d_in[30];
    float* out = (float*)d_out;

    const int N = in_sizes[3];
    const int B = in_sizes[0] / 512;

    __nv_bfloat16 *nf, *s1b, *s2b, *wt1, *wt2, *wt3;
    float *ff, *sf, *dd1, *dd2, *dd3, *comb, *f1;
    cudaGetSymbolAddress((void**)&nf,   g_nf);
    cudaGetSymbolAddress((void**)&s1b,  g_s1b);
    cudaGetSymbolAddress((void**)&s2b,  g_s2b);
    cudaGetSymbolAddress((void**)&wt1,  g_wt1);
    cudaGetSymbolAddress((void**)&wt2,  g_wt2);
    cudaGetSymbolAddress((void**)&wt3,  g_wt3);
    cudaGetSymbolAddress((void**)&ff,   g_ff);
    cudaGetSymbolAddress((void**)&sf,   g_sf);
    cudaGetSymbolAddress((void**)&dd1,  g_d1);
    cudaGetSymbolAddress((void**)&dd2,  g_d2);
    cudaGetSymbolAddress((void**)&dd3,  g_d3);
    cudaGetSymbolAddress((void**)&comb, g_comb);
    cudaGetSymbolAddress((void**)&f1,   g_f1);

    const int gy = (N + 63) / 64;
    const size_t nfe = (size_t)N * 256;

    // --- prologue conversions ---
    f32_to_bf16_kernel<<<(int)((nfe / 2 + 255) / 256), 256>>>(nodef, nf, nfe);
    conv_transpose_kernel<<<(256 * 256 + 255) / 256, 256>>>(ff_w1, wt1, 256, 256);
    conv_transpose_kernel<<<(256 * 128 + 255) / 256, 256>>>(ff_w2, wt2, 256, 128);
    conv_transpose_kernel<<<(128 * 300 + 255) / 256, 256>>>(ff_w3, wt3, 128, 300);
    seg_kernel<<<1, 512>>>(batch, N, B);
    zero_kernel<<<(B * 600 + 255) / 256, 256>>>(sf, B * 600);

    // --- node MLP (bf16 tensor cores, fused LN+SiLU) ---
    bf16_gemm<64, 256, 2, 4, true,  false, true ><<<dim3(1, gy), 256>>>(
        nf,  wt1, ff_b1, ff_g1, ff_bb1, s1b, N, 256, 256);
    bf16_gemm<64, 128, 4, 2, true,  false, true ><<<dim3(1, gy), 256>>>(
        s1b, wt2, ff_b2, ff_g2, ff_bb2, s2b, N, 128, 256);
    bf16_gemm<64, 64,  4, 2, false, true,  false><<<dim3(5, gy), 256>>>(
        s2b, wt3, ff_b3, nullptr, nullptr, ff, N, 300, 128);

    // --- structure factors ---
    const int CHUNKS = 8;
    accum_kernel<<<dim3(B, CHUNKS), 320>>>(ff, pos, hkl, sf, CHUNKS);

    // --- diffraction net (B rows) ---
    sgemm_small<<<dim3(8, (B + 63) / 64), 256>>>(sf, dn_w1, dn_b1, nullptr, dd1, B, 512, 600);
    ln_silu_kernel<<<B, 512>>>(dd1, dn_g1, dn_bb1, 512, 1);
    sgemm_small<<<dim3(4, (B + 63) / 64), 256>>>(dd1, dn_w2, dn_b2, nullptr, dd2, B, 256, 512);
    ln_silu_kernel<<<B, 256>>>(dd2, dn_g2, dn_bb2, 256, 1);
    sgemm_small<<<dim3(8, (B + 63) / 64), 256>>>(dd2, dn_w3, dn_b3, nullptr, dd3, B, 512, 256);

    // --- fusion net + residual ---
    concat_kernel<<<B, 256>>>(graph, dd3, comb, 512, 512);
    sgemm_small<<<dim3(8, (B + 63) / 64), 256>>>(comb, fn_w1, fn_b1, nullptr, f1, B, 512, 1024);
    ln_silu_kernel<<<B, 512>>>(f1, fn_g, fn_bb, 512, 1);
    sgemm_small<<<dim3(8, (B + 63) / 64), 256>>>(f1, fn_w2, fn_b2, graph, out, B, 512, 512);
}